// round 11
// baseline (speedup 1.0000x reference)
#include <cuda_runtime.h>
#include <math.h>

static constexpr int kB  = 2;
static constexpr int kNX = 512;
static constexpr int kNC = 4096;
static constexpr int kD  = 1024;
static constexpr int kH  = 16;
static constexpr int kHD = 64;
#define ATT_SCALE 0.125f   // HD^-0.5

// Scratch (allocation-free rule: __device__ globals)
__device__ float g_xn[kB * kNX * kD];
__device__ float g_q [kB * kNX * kD];
__device__ float g_a [kB * kNX * kD];

// ---------------------------------------------------------------------------
// packed fp32 (f32x2) helpers — Blackwell FFMA2 path
// ---------------------------------------------------------------------------
using u64 = unsigned long long;

__device__ __forceinline__ u64 ffma2(u64 a, u64 b, u64 c) {
    u64 d;
    asm("fma.rn.f32x2 %0, %1, %2, %3;" : "=l"(d) : "l"(a), "l"(b), "l"(c));
    return d;
}
__device__ __forceinline__ u64 fmul2(u64 a, u64 b) {
    u64 d;
    asm("mul.rn.f32x2 %0, %1, %2;" : "=l"(d) : "l"(a), "l"(b));
    return d;
}
__device__ __forceinline__ u64 dup2(float v) {
    u64 d;
    asm("mov.b64 %0, {%1, %1};" : "=l"(d) : "f"(v));
    return d;
}
__device__ __forceinline__ float2 unpk(u64 v) {
    float2 f;
    asm("mov.b64 {%0, %1}, %2;" : "=f"(f.x), "=f"(f.y) : "l"(v));
    return f;
}

// parity-padded row offset: stride 66 + 2 on odd rows -> every row 16B-aligned
__device__ __forceinline__ int prow(int r) { return r * 66 + 2 * (r & 1); }

// ---------------------------------------------------------------------------
// LayerNorm: one block per row of x, D=1024, 256 threads (1 float4 each)
// ---------------------------------------------------------------------------
__global__ __launch_bounds__(256) void ln_kernel(
    const float* __restrict__ x, const float* __restrict__ w,
    const float* __restrict__ bb, float* __restrict__ out)
{
    int row = blockIdx.x;
    int tid = threadIdx.x;
    float4 v = reinterpret_cast<const float4*>(x + (size_t)row * kD)[tid];
    float s  = v.x + v.y + v.z + v.w;
    float sq = v.x*v.x + v.y*v.y + v.z*v.z + v.w*v.w;
    #pragma unroll
    for (int o = 16; o; o >>= 1) {
        s  += __shfl_xor_sync(0xffffffffu, s,  o);
        sq += __shfl_xor_sync(0xffffffffu, sq, o);
    }
    __shared__ float ss[8], ssq[8];
    int wid = tid >> 5, lid = tid & 31;
    if (lid == 0) { ss[wid] = s; ssq[wid] = sq; }
    __syncthreads();
    if (wid == 0) {
        s  = (lid < 8) ? ss[lid]  : 0.f;
        sq = (lid < 8) ? ssq[lid] : 0.f;
        #pragma unroll
        for (int o = 4; o; o >>= 1) {
            s  += __shfl_xor_sync(0xffffffffu, s,  o);
            sq += __shfl_xor_sync(0xffffffffu, sq, o);
        }
        if (lid == 0) { ss[0] = s; ssq[0] = sq; }
    }
    __syncthreads();
    float mu   = ss[0] * (1.f / kD);
    float var  = ssq[0] * (1.f / kD) - mu * mu;
    float rstd = rsqrtf(var + 1e-5f);
    float4 w4 = reinterpret_cast<const float4*>(w)[tid];
    float4 b4 = reinterpret_cast<const float4*>(bb)[tid];
    float4 o4;
    o4.x = (v.x - mu) * rstd * w4.x + b4.x;
    o4.y = (v.y - mu) * rstd * w4.y + b4.y;
    o4.z = (v.z - mu) * rstd * w4.z + b4.z;
    o4.w = (v.w - mu) * rstd * w4.w + b4.w;
    reinterpret_cast<float4*>(out + (size_t)row * kD)[tid] = o4;
}

// ---------------------------------------------------------------------------
// SGEMM (f32x2): C[M,N] = A[M,K] @ B[K,N]. BM=128, BN=64, BK=16, 256 thr,
// micro 8(m) x 4(n), n-pairs packed into FFMA2, A dup'd at read time.
// ---------------------------------------------------------------------------
__device__ __forceinline__ int atrow(int k) { return k * 130 + 2 * (k & 1); }

__global__ __launch_bounds__(256) void sgemm_kernel(
    const float* __restrict__ A, const float* __restrict__ Bm,
    float* __restrict__ C, int M, int N, int K)
{
    __shared__ __align__(16) float At[16 * 130 + 8];  // [k][m], parity pad
    __shared__ __align__(16) float Bs[16][68];        // [k][n]

    int tid = threadIdx.x;
    int tx = tid & 15, ty = tid >> 4;
    int m0 = blockIdx.y * 128, n0 = blockIdx.x * 64;

    u64 acc[8][2];
    #pragma unroll
    for (int i = 0; i < 8; i++) { acc[i][0] = 0ull; acc[i][1] = 0ull; }

    for (int k0 = 0; k0 < K; k0 += 16) {
        #pragma unroll
        for (int j = 0; j < 2; j++) {
            int idx = tid + 256 * j;
            int m = idx >> 2, k4 = idx & 3;
            float4 v = *reinterpret_cast<const float4*>(
                A + (size_t)(m0 + m) * K + k0 + k4 * 4);
            int kk = k4 * 4;
            At[atrow(kk + 0) + m] = v.x;
            At[atrow(kk + 1) + m] = v.y;
            At[atrow(kk + 2) + m] = v.z;
            At[atrow(kk + 3) + m] = v.w;
        }
        {
            int kk = tid >> 4, n4 = tid & 15;
            float4 v = *reinterpret_cast<const float4*>(
                Bm + (size_t)(k0 + kk) * N + n0 + n4 * 4);
            *reinterpret_cast<float4*>(&Bs[kk][n4 * 4]) = v;
        }
        __syncthreads();
        const float* ab = At + ty * 8;
        #pragma unroll
        for (int kk = 0; kk < 16; kk++) {
            ulonglong2 b2 = *reinterpret_cast<const ulonglong2*>(&Bs[kk][tx * 4]);
            float4 a0 = *reinterpret_cast<const float4*>(ab);
            float4 a1 = *reinterpret_cast<const float4*>(ab + 4);
            ab += (kk & 1) ? 128 : 132;
            u64 d;
            d = dup2(a0.x); acc[0][0] = ffma2(d, b2.x, acc[0][0]); acc[0][1] = ffma2(d, b2.y, acc[0][1]);
            d = dup2(a0.y); acc[1][0] = ffma2(d, b2.x, acc[1][0]); acc[1][1] = ffma2(d, b2.y, acc[1][1]);
            d = dup2(a0.z); acc[2][0] = ffma2(d, b2.x, acc[2][0]); acc[2][1] = ffma2(d, b2.y, acc[2][1]);
            d = dup2(a0.w); acc[3][0] = ffma2(d, b2.x, acc[3][0]); acc[3][1] = ffma2(d, b2.y, acc[3][1]);
            d = dup2(a1.x); acc[4][0] = ffma2(d, b2.x, acc[4][0]); acc[4][1] = ffma2(d, b2.y, acc[4][1]);
            d = dup2(a1.y); acc[5][0] = ffma2(d, b2.x, acc[5][0]); acc[5][1] = ffma2(d, b2.y, acc[5][1]);
            d = dup2(a1.z); acc[6][0] = ffma2(d, b2.x, acc[6][0]); acc[6][1] = ffma2(d, b2.y, acc[6][1]);
            d = dup2(a1.w); acc[7][0] = ffma2(d, b2.x, acc[7][0]); acc[7][1] = ffma2(d, b2.y, acc[7][1]);
        }
        __syncthreads();
    }
    #pragma unroll
    for (int rr = 0; rr < 8; rr++) {
        float2 c01 = unpk(acc[rr][0]);
        float2 c23 = unpk(acc[rr][1]);
        float4 o = make_float4(c01.x, c01.y, c23.x, c23.y);
        *reinterpret_cast<float4*>(
            C + (size_t)(m0 + ty * 8 + rr) * N + n0 + tx * 4) = o;
    }
}

// ---------------------------------------------------------------------------
// kv0: out[b][h][n][d] = c[b][n][h*64+d]  (float4 granularity)
// ---------------------------------------------------------------------------
__global__ __launch_bounds__(256) void kv0_kernel(
    const float* __restrict__ c, float4* __restrict__ out)
{
    int i = blockIdx.x * 256 + threadIdx.x;
    int d4 = i & 15;
    int n  = (i >> 4) & (kNC - 1);
    int h  = (i >> 16) & (kH - 1);
    int b  = i >> 20;
    const float4* src = reinterpret_cast<const float4*>(c);
    out[i] = src[(size_t)(b * kNC + n) * (kD / 4) + h * 16 + d4];
}

// ---------------------------------------------------------------------------
// Flash attention (fp32, FFMA2). One block per (b, h, 64-query tile).
// micro: 4 q (ty) x 4 keys (tx*4..+3, packed as 2 f32x2 pairs).
// ---------------------------------------------------------------------------
static constexpr int QT_OFF = 0;
static constexpr int KT_OFF = 4240;
static constexpr int KS_OFF = 8480;
static constexpr int PS_OFF = 12832;
static constexpr int SMEM_ATTN_FLOATS = 17072;
static constexpr int SMEM_ATTN_BYTES  = SMEM_ATTN_FLOATS * 4;

__global__ __launch_bounds__(256, 2) void attn_kernel(
    const float* __restrict__ q_s, const float* __restrict__ ctx,
    const int* __restrict__ mask, float* __restrict__ a_out)
{
    extern __shared__ float sm[];
    float* Qt = sm + QT_OFF;   // [prow(q)][k]   scaled q
    float* Kt = sm + KT_OFF;   // [prow(k)][key] transposed K
    float* Ks = sm + KS_OFF;   // [key*68 + d]   K = V
    float* Ps = sm + PS_OFF;   // [prow(q)][c]   probabilities

    int tid = threadIdx.x;
    int tx = tid & 15, ty = tid >> 4;
    int qt = blockIdx.x & 7;
    int h  = (blockIdx.x >> 3) & 15;
    int b  = blockIdx.x >> 7;
    int q0 = qt * 64;
    int kx = tx * 4;

    int qrow[4];
    #pragma unroll
    for (int rr = 0; rr < 4; rr++) qrow[rr] = prow(ty * 4 + rr);

    {   // load Q tile (pre-scaled), q-major
        const float* src = q_s + ((size_t)(b * kNX + q0)) * kD + h * kHD;
        #pragma unroll
        for (int j = 0; j < 4; j++) {
            int idx = tid + 256 * j;
            int r = idx >> 4, d4 = idx & 15;
            float4 v = *reinterpret_cast<const float4*>(src + (size_t)r * kD + d4 * 4);
            v.x *= ATT_SCALE; v.y *= ATT_SCALE; v.z *= ATT_SCALE; v.w *= ATT_SCALE;
            *reinterpret_cast<float4*>(&Qt[prow(r) + d4 * 4]) = v;
        }
    }

    u64 oA[4][2];
    #pragma unroll
    for (int i = 0; i < 4; i++) { oA[i][0] = 0ull; oA[i][1] = 0ull; }
    float mi[4] = {-1e30f, -1e30f, -1e30f, -1e30f};
    float li[4] = {0.f, 0.f, 0.f, 0.f};

    const int NT = kNX / 64 + kNC / 64;   // 72
    for (int t = 0; t < NT; t++) {
        __syncthreads();   // prev PV done before overwriting Ks/Kt
        const float* src = (t < 8)
            ? q_s + ((size_t)(b * kNX + t * 64)) * kD + h * kHD
            : ctx + ((size_t)(b * kNC + (t - 8) * 64)) * kD + h * kHD;
        #pragma unroll
        for (int j = 0; j < 4; j++) {
            int idx = tid + 256 * j;
            int r = idx >> 4, d4 = idx & 15;
            float4 v = *reinterpret_cast<const float4*>(src + (size_t)r * kD + d4 * 4);
            *reinterpret_cast<float4*>(&Ks[r * 68 + d4 * 4]) = v;
            int d = d4 * 4;
            Kt[prow(d + 0) + r] = v.x;
            Kt[prow(d + 1) + r] = v.y;
            Kt[prow(d + 2) + r] = v.z;
            Kt[prow(d + 3) + r] = v.w;
        }
        int4 mreg[4];
        bool masked_tile = (t >= 8);
        if (masked_tile) {
            const int* mb = mask + ((size_t)(b * kNX + q0 + ty * 4)) * kNC
                                 + (size_t)(t - 8) * 64 + kx;
            #pragma unroll
            for (int rr = 0; rr < 4; rr++)
                mreg[rr] = *reinterpret_cast<const int4*>(mb + (size_t)rr * kNC);
        }
        __syncthreads();

        // ---- S = (q*scale) . k over HD=64, packed key pairs ----
        u64 sA[4][2];
        #pragma unroll
        for (int i = 0; i < 4; i++) { sA[i][0] = 0ull; sA[i][1] = 0ull; }
        {
            const float* kb = Kt + kx;
            #pragma unroll 4
            for (int it = 0; it < 16; it++) {
                ulonglong2 k0 = *reinterpret_cast<const ulonglong2*>(kb);
                ulonglong2 k1 = *reinterpret_cast<const ulonglong2*>(kb + 68);
                ulonglong2 k2 = *reinterpret_cast<const ulonglong2*>(kb + 132);
                ulonglong2 k3 = *reinterpret_cast<const ulonglong2*>(kb + 200);
                kb += 264;
                int k = it * 4;
                #pragma unroll
                for (int rr = 0; rr < 4; rr++) {
                    float4 q4 = *reinterpret_cast<const float4*>(&Qt[qrow[rr] + k]);
                    u64 d;
                    d = dup2(q4.x); sA[rr][0] = ffma2(d, k0.x, sA[rr][0]); sA[rr][1] = ffma2(d, k0.y, sA[rr][1]);
                    d = dup2(q4.y); sA[rr][0] = ffma2(d, k1.x, sA[rr][0]); sA[rr][1] = ffma2(d, k1.y, sA[rr][1]);
                    d = dup2(q4.z); sA[rr][0] = ffma2(d, k2.x, sA[rr][0]); sA[rr][1] = ffma2(d, k2.y, sA[rr][1]);
                    d = dup2(q4.w); sA[rr][0] = ffma2(d, k3.x, sA[rr][0]); sA[rr][1] = ffma2(d, k3.y, sA[rr][1]);
                }
            }
        }

        // ---- online softmax (16 tx threads share each q row) ----
        #pragma unroll
        for (int rr = 0; rr < 4; rr++) {
            float2 s01 = unpk(sA[rr][0]);
            float2 s23 = unpk(sA[rr][1]);
            float s0 = s01.x, s1 = s01.y, s2 = s23.x, s3 = s23.y;
            if (masked_tile) {
                if (!mreg[rr].x) s0 = -1e30f;
                if (!mreg[rr].y) s1 = -1e30f;
                if (!mreg[rr].z) s2 = -1e30f;
                if (!mreg[rr].w) s3 = -1e30f;
            }
            float mx = fmaxf(fmaxf(s0, s1), fmaxf(s2, s3));
            #pragma unroll
            for (int off = 8; off; off >>= 1)
                mx = fmaxf(mx, __shfl_xor_sync(0xffffffffu, mx, off, 16));
            float mnew = fmaxf(mi[rr], mx);
            float corr = __expf(mi[rr] - mnew);
            float4 p;
            p.x = __expf(s0 - mnew);
            p.y = __expf(s1 - mnew);
            p.z = __expf(s2 - mnew);
            p.w = __expf(s3 - mnew);
            float ssum = p.x + p.y + p.z + p.w;
            #pragma unroll
            for (int off = 8; off; off >>= 1)
                ssum += __shfl_xor_sync(0xffffffffu, ssum, off, 16);
            li[rr] = li[rr] * corr + ssum;
            mi[rr] = mnew;
            u64 cd = dup2(corr);
            oA[rr][0] = fmul2(oA[rr][0], cd);
            oA[rr][1] = fmul2(oA[rr][1], cd);
            *reinterpret_cast<float4*>(&Ps[qrow[rr] + kx]) = p;
        }
        __syncthreads();   // Ps visible

        // ---- O += P . V, packed d pairs ----
        {
            const float* vb = Ks + kx;
            #pragma unroll 4
            for (int it = 0; it < 16; it++) {
                ulonglong2 v0 = *reinterpret_cast<const ulonglong2*>(vb);
                ulonglong2 v1 = *reinterpret_cast<const ulonglong2*>(vb + 68);
                ulonglong2 v2 = *reinterpret_cast<const ulonglong2*>(vb + 136);
                ulonglong2 v3 = *reinterpret_cast<const ulonglong2*>(vb + 204);
                vb += 272;
                int c = it * 4;
                #pragma unroll
                for (int rr = 0; rr < 4; rr++) {
                    float4 p4 = *reinterpret_cast<const float4*>(&Ps[qrow[rr] + c]);
                    u64 d;
                    d = dup2(p4.x); oA[rr][0] = ffma2(d, v0.x, oA[rr][0]); oA[rr][1] = ffma2(d, v0.y, oA[rr][1]);
                    d = dup2(p4.y); oA[rr][0] = ffma2(d, v1.x, oA[rr][0]); oA[rr][1] = ffma2(d, v1.y, oA[rr][1]);
                    d = dup2(p4.z); oA[rr][0] = ffma2(d, v2.x, oA[rr][0]); oA[rr][1] = ffma2(d, v2.y, oA[rr][1]);
                    d = dup2(p4.w); oA[rr][0] = ffma2(d, v3.x, oA[rr][0]); oA[rr][1] = ffma2(d, v3.y, oA[rr][1]);
                }
            }
        }
    }

    // normalize + write a in (B, NX, H*HD) layout
    #pragma unroll
    for (int rr = 0; rr < 4; rr++) {
        float inv = 1.f / li[rr];
        float2 o01 = unpk(oA[rr][0]);
        float2 o23 = unpk(oA[rr][1]);
        float4 o = make_float4(o01.x * inv, o01.y * inv, o23.x * inv, o23.y * inv);
        int row = q0 + ty * 4 + rr;
        *reinterpret_cast<float4*>(
            a_out + ((size_t)(b * kNX + row)) * kD + h * kHD + kx) = o;
    }
}

// ---------------------------------------------------------------------------
extern "C" void kernel_launch(void* const* d_in, const int* in_sizes, int n_in,
                              void* d_out, int out_size)
{
    (void)in_sizes; (void)n_in; (void)out_size;
    const float* x    = (const float*)d_in[0];
    const float* c    = (const float*)d_in[1];
    const int*   mask = (const int*)  d_in[2];
    const float* lnw  = (const float*)d_in[3];
    const float* lnb  = (const float*)d_in[4];
    const float* Wq   = (const float*)d_in[5];
    const float* Wo   = (const float*)d_in[6];

    float* o_out  = (float*)d_out;
    float* kv_out = o_out + (size_t)kB * kNX * kD;

    void *p_xn, *p_q, *p_a;
    cudaGetSymbolAddress(&p_xn, g_xn);
    cudaGetSymbolAddress(&p_q,  g_q);
    cudaGetSymbolAddress(&p_a,  g_a);
    float* xn = (float*)p_xn;
    float* q  = (float*)p_q;
    float* a  = (float*)p_a;

    cudaFuncSetAttribute(attn_kernel,
                         cudaFuncAttributeMaxDynamicSharedMemorySize,
                         SMEM_ATTN_BYTES);

    const int M = kB * kNX;   // 1024

    // 1) LayerNorm
    ln_kernel<<<M, 256>>>(x, lnw, lnb, xn);
    // 2) q = xn @ Wq
    sgemm_kernel<<<dim3(kD / 64, M / 128), 256>>>(xn, Wq, q, M, kD, kD);
    // 3) kv0 output (independent)
    kv0_kernel<<<(kB * kH * kNC * kHD / 4) / 256, 256>>>(c, (float4*)kv_out);
    // 4) attention
    attn_kernel<<<kB * kH * (kNX / 64), 256, SMEM_ATTN_BYTES>>>(q, c, mask, a);
    // 5) o = a @ Wo
    sgemm_kernel<<<dim3(kD / 64, M / 128), 256>>>(a, Wo, o_out, M, kD, kD);
}

// round 12
// speedup vs baseline: 1.0015x; 1.0015x over previous
#include <cuda_runtime.h>
#include <math.h>

static constexpr int kB  = 2;
static constexpr int kNX = 512;
static constexpr int kNC = 4096;
static constexpr int kD  = 1024;
static constexpr int kH  = 16;
static constexpr int kHD = 64;
#define ATT_SCALE 0.125f   // HD^-0.5

// Scratch (allocation-free rule: __device__ globals)
__device__ float g_xn[kB * kNX * kD];
__device__ float g_q [kB * kNX * kD];
__device__ float g_a [kB * kNX * kD];

// ---------------------------------------------------------------------------
// packed fp32 (f32x2) helpers — Blackwell FFMA2 path
// ---------------------------------------------------------------------------
using u64 = unsigned long long;

__device__ __forceinline__ u64 ffma2(u64 a, u64 b, u64 c) {
    u64 d;
    asm("fma.rn.f32x2 %0, %1, %2, %3;" : "=l"(d) : "l"(a), "l"(b), "l"(c));
    return d;
}
__device__ __forceinline__ u64 fmul2(u64 a, u64 b) {
    u64 d;
    asm("mul.rn.f32x2 %0, %1, %2;" : "=l"(d) : "l"(a), "l"(b));
    return d;
}
__device__ __forceinline__ u64 dup2(float v) {
    u64 d;
    asm("mov.b64 %0, {%1, %1};" : "=l"(d) : "f"(v));
    return d;
}
__device__ __forceinline__ float2 unpk(u64 v) {
    float2 f;
    asm("mov.b64 {%0, %1}, %2;" : "=f"(f.x), "=f"(f.y) : "l"(v));
    return f;
}

// parity-padded row offset: stride 66 + 2 on odd rows -> every row 16B-aligned
__device__ __forceinline__ int prow(int r) { return r * 66 + 2 * (r & 1); }

// ---------------------------------------------------------------------------
// LayerNorm: one block per row of x, D=1024, 256 threads (1 float4 each)
// ---------------------------------------------------------------------------
__global__ __launch_bounds__(256) void ln_kernel(
    const float* __restrict__ x, const float* __restrict__ w,
    const float* __restrict__ bb, float* __restrict__ out)
{
    int row = blockIdx.x;
    int tid = threadIdx.x;
    float4 v = reinterpret_cast<const float4*>(x + (size_t)row * kD)[tid];
    float s  = v.x + v.y + v.z + v.w;
    float sq = v.x*v.x + v.y*v.y + v.z*v.z + v.w*v.w;
    #pragma unroll
    for (int o = 16; o; o >>= 1) {
        s  += __shfl_xor_sync(0xffffffffu, s,  o);
        sq += __shfl_xor_sync(0xffffffffu, sq, o);
    }
    __shared__ float ss[8], ssq[8];
    int wid = tid >> 5, lid = tid & 31;
    if (lid == 0) { ss[wid] = s; ssq[wid] = sq; }
    __syncthreads();
    if (wid == 0) {
        s  = (lid < 8) ? ss[lid]  : 0.f;
        sq = (lid < 8) ? ssq[lid] : 0.f;
        #pragma unroll
        for (int o = 4; o; o >>= 1) {
            s  += __shfl_xor_sync(0xffffffffu, s,  o);
            sq += __shfl_xor_sync(0xffffffffu, sq, o);
        }
        if (lid == 0) { ss[0] = s; ssq[0] = sq; }
    }
    __syncthreads();
    float mu   = ss[0] * (1.f / kD);
    float var  = ssq[0] * (1.f / kD) - mu * mu;
    float rstd = rsqrtf(var + 1e-5f);
    float4 w4 = reinterpret_cast<const float4*>(w)[tid];
    float4 b4 = reinterpret_cast<const float4*>(bb)[tid];
    float4 o4;
    o4.x = (v.x - mu) * rstd * w4.x + b4.x;
    o4.y = (v.y - mu) * rstd * w4.y + b4.y;
    o4.z = (v.z - mu) * rstd * w4.z + b4.z;
    o4.w = (v.w - mu) * rstd * w4.w + b4.w;
    reinterpret_cast<float4*>(out + (size_t)row * kD)[tid] = o4;
}

// ---------------------------------------------------------------------------
// SGEMM (f32x2): C[M,N] = A[M,K] @ B[K,N]. BM=128, BN=64, BK=16, 256 thr,
// micro 8(m) x 4(n), n-pairs packed into FFMA2, A dup'd at read time.
// ---------------------------------------------------------------------------
__device__ __forceinline__ int atrow(int k) { return k * 130 + 2 * (k & 1); }

__global__ __launch_bounds__(256) void sgemm_kernel(
    const float* __restrict__ A, const float* __restrict__ Bm,
    float* __restrict__ C, int M, int N, int K)
{
    __shared__ __align__(16) float At[16 * 130 + 8];  // [k][m], parity pad
    __shared__ __align__(16) float Bs[16][68];        // [k][n]

    int tid = threadIdx.x;
    int tx = tid & 15, ty = tid >> 4;
    int m0 = blockIdx.y * 128, n0 = blockIdx.x * 64;

    u64 acc[8][2];
    #pragma unroll
    for (int i = 0; i < 8; i++) { acc[i][0] = 0ull; acc[i][1] = 0ull; }

    for (int k0 = 0; k0 < K; k0 += 16) {
        #pragma unroll
        for (int j = 0; j < 2; j++) {
            int idx = tid + 256 * j;
            int m = idx >> 2, k4 = idx & 3;
            float4 v = *reinterpret_cast<const float4*>(
                A + (size_t)(m0 + m) * K + k0 + k4 * 4);
            int kk = k4 * 4;
            At[atrow(kk + 0) + m] = v.x;
            At[atrow(kk + 1) + m] = v.y;
            At[atrow(kk + 2) + m] = v.z;
            At[atrow(kk + 3) + m] = v.w;
        }
        {
            int kk = tid >> 4, n4 = tid & 15;
            float4 v = *reinterpret_cast<const float4*>(
                Bm + (size_t)(k0 + kk) * N + n0 + n4 * 4);
            *reinterpret_cast<float4*>(&Bs[kk][n4 * 4]) = v;
        }
        __syncthreads();
        const float* ab = At + ty * 8;
        #pragma unroll
        for (int kk = 0; kk < 16; kk++) {
            ulonglong2 b2 = *reinterpret_cast<const ulonglong2*>(&Bs[kk][tx * 4]);
            float4 a0 = *reinterpret_cast<const float4*>(ab);
            float4 a1 = *reinterpret_cast<const float4*>(ab + 4);
            ab += (kk & 1) ? 128 : 132;
            u64 d;
            d = dup2(a0.x); acc[0][0] = ffma2(d, b2.x, acc[0][0]); acc[0][1] = ffma2(d, b2.y, acc[0][1]);
            d = dup2(a0.y); acc[1][0] = ffma2(d, b2.x, acc[1][0]); acc[1][1] = ffma2(d, b2.y, acc[1][1]);
            d = dup2(a0.z); acc[2][0] = ffma2(d, b2.x, acc[2][0]); acc[2][1] = ffma2(d, b2.y, acc[2][1]);
            d = dup2(a0.w); acc[3][0] = ffma2(d, b2.x, acc[3][0]); acc[3][1] = ffma2(d, b2.y, acc[3][1]);
            d = dup2(a1.x); acc[4][0] = ffma2(d, b2.x, acc[4][0]); acc[4][1] = ffma2(d, b2.y, acc[4][1]);
            d = dup2(a1.y); acc[5][0] = ffma2(d, b2.x, acc[5][0]); acc[5][1] = ffma2(d, b2.y, acc[5][1]);
            d = dup2(a1.z); acc[6][0] = ffma2(d, b2.x, acc[6][0]); acc[6][1] = ffma2(d, b2.y, acc[6][1]);
            d = dup2(a1.w); acc[7][0] = ffma2(d, b2.x, acc[7][0]); acc[7][1] = ffma2(d, b2.y, acc[7][1]);
        }
        __syncthreads();
    }
    #pragma unroll
    for (int rr = 0; rr < 8; rr++) {
        float2 c01 = unpk(acc[rr][0]);
        float2 c23 = unpk(acc[rr][1]);
        float4 o = make_float4(c01.x, c01.y, c23.x, c23.y);
        *reinterpret_cast<float4*>(
            C + (size_t)(m0 + ty * 8 + rr) * N + n0 + tx * 4) = o;
    }
}

// ---------------------------------------------------------------------------
// kv0: out[b][h][n][d] = c[b][n][h*64+d]  (float4 granularity)
// ---------------------------------------------------------------------------
__global__ __launch_bounds__(256) void kv0_kernel(
    const float* __restrict__ c, float4* __restrict__ out)
{
    int i = blockIdx.x * 256 + threadIdx.x;
    int d4 = i & 15;
    int n  = (i >> 4) & (kNC - 1);
    int h  = (i >> 16) & (kH - 1);
    int b  = i >> 20;
    const float4* src = reinterpret_cast<const float4*>(c);
    out[i] = src[(size_t)(b * kNC + n) * (kD / 4) + h * 16 + d4];
}

// ---------------------------------------------------------------------------
// Flash attention (fp32, FFMA2). One block per (b, h, 64-query tile).
// micro: 4 q (ty) x 4 keys (tx*4..+3, packed as 2 f32x2 pairs).
// ---------------------------------------------------------------------------
static constexpr int QT_OFF = 0;
static constexpr int KT_OFF = 4240;
static constexpr int KS_OFF = 8480;
static constexpr int PS_OFF = 12832;
static constexpr int SMEM_ATTN_FLOATS = 17072;
static constexpr int SMEM_ATTN_BYTES  = SMEM_ATTN_FLOATS * 4;

__global__ __launch_bounds__(256, 2) void attn_kernel(
    const float* __restrict__ q_s, const float* __restrict__ ctx,
    const int* __restrict__ mask, float* __restrict__ a_out)
{
    extern __shared__ float sm[];
    float* Qt = sm + QT_OFF;   // [prow(q)][k]   scaled q
    float* Kt = sm + KT_OFF;   // [prow(k)][key] transposed K
    float* Ks = sm + KS_OFF;   // [key*68 + d]   K = V
    float* Ps = sm + PS_OFF;   // [prow(q)][c]   probabilities

    int tid = threadIdx.x;
    int tx = tid & 15, ty = tid >> 4;
    int qt = blockIdx.x & 7;
    int h  = (blockIdx.x >> 3) & 15;
    int b  = blockIdx.x >> 7;
    int q0 = qt * 64;
    int kx = tx * 4;

    int qrow[4];
    #pragma unroll
    for (int rr = 0; rr < 4; rr++) qrow[rr] = prow(ty * 4 + rr);

    {   // load Q tile (pre-scaled), q-major
        const float* src = q_s + ((size_t)(b * kNX + q0)) * kD + h * kHD;
        #pragma unroll
        for (int j = 0; j < 4; j++) {
            int idx = tid + 256 * j;
            int r = idx >> 4, d4 = idx & 15;
            float4 v = *reinterpret_cast<const float4*>(src + (size_t)r * kD + d4 * 4);
            v.x *= ATT_SCALE; v.y *= ATT_SCALE; v.z *= ATT_SCALE; v.w *= ATT_SCALE;
            *reinterpret_cast<float4*>(&Qt[prow(r) + d4 * 4]) = v;
        }
    }

    u64 oA[4][2];
    #pragma unroll
    for (int i = 0; i < 4; i++) { oA[i][0] = 0ull; oA[i][1] = 0ull; }
    float mi[4] = {-1e30f, -1e30f, -1e30f, -1e30f};
    float li[4] = {0.f, 0.f, 0.f, 0.f};

    const int NT = kNX / 64 + kNC / 64;   // 72
    for (int t = 0; t < NT; t++) {
        __syncthreads();   // prev PV done before overwriting Ks/Kt
        const float* src = (t < 8)
            ? q_s + ((size_t)(b * kNX + t * 64)) * kD + h * kHD
            : ctx + ((size_t)(b * kNC + (t - 8) * 64)) * kD + h * kHD;
        #pragma unroll
        for (int j = 0; j < 4; j++) {
            int idx = tid + 256 * j;
            int r = idx >> 4, d4 = idx & 15;
            float4 v = *reinterpret_cast<const float4*>(src + (size_t)r * kD + d4 * 4);
            *reinterpret_cast<float4*>(&Ks[r * 68 + d4 * 4]) = v;
            int d = d4 * 4;
            Kt[prow(d + 0) + r] = v.x;
            Kt[prow(d + 1) + r] = v.y;
            Kt[prow(d + 2) + r] = v.z;
            Kt[prow(d + 3) + r] = v.w;
        }
        int4 mreg[4];
        bool masked_tile = (t >= 8);
        if (masked_tile) {
            const int* mb = mask + ((size_t)(b * kNX + q0 + ty * 4)) * kNC
                                 + (size_t)(t - 8) * 64 + kx;
            #pragma unroll
            for (int rr = 0; rr < 4; rr++)
                mreg[rr] = *reinterpret_cast<const int4*>(mb + (size_t)rr * kNC);
        }
        __syncthreads();

        // ---- S = (q*scale) . k over HD=64, packed key pairs ----
        u64 sA[4][2];
        #pragma unroll
        for (int i = 0; i < 4; i++) { sA[i][0] = 0ull; sA[i][1] = 0ull; }
        {
            const float* kb = Kt + kx;
            #pragma unroll 4
            for (int it = 0; it < 16; it++) {
                ulonglong2 k0 = *reinterpret_cast<const ulonglong2*>(kb);
                ulonglong2 k1 = *reinterpret_cast<const ulonglong2*>(kb + 68);
                ulonglong2 k2 = *reinterpret_cast<const ulonglong2*>(kb + 132);
                ulonglong2 k3 = *reinterpret_cast<const ulonglong2*>(kb + 200);
                kb += 264;
                int k = it * 4;
                #pragma unroll
                for (int rr = 0; rr < 4; rr++) {
                    float4 q4 = *reinterpret_cast<const float4*>(&Qt[qrow[rr] + k]);
                    u64 d;
                    d = dup2(q4.x); sA[rr][0] = ffma2(d, k0.x, sA[rr][0]); sA[rr][1] = ffma2(d, k0.y, sA[rr][1]);
                    d = dup2(q4.y); sA[rr][0] = ffma2(d, k1.x, sA[rr][0]); sA[rr][1] = ffma2(d, k1.y, sA[rr][1]);
                    d = dup2(q4.z); sA[rr][0] = ffma2(d, k2.x, sA[rr][0]); sA[rr][1] = ffma2(d, k2.y, sA[rr][1]);
                    d = dup2(q4.w); sA[rr][0] = ffma2(d, k3.x, sA[rr][0]); sA[rr][1] = ffma2(d, k3.y, sA[rr][1]);
                }
            }
        }

        // ---- online softmax (16 tx threads share each q row) ----
        #pragma unroll
        for (int rr = 0; rr < 4; rr++) {
            float2 s01 = unpk(sA[rr][0]);
            float2 s23 = unpk(sA[rr][1]);
            float s0 = s01.x, s1 = s01.y, s2 = s23.x, s3 = s23.y;
            if (masked_tile) {
                if (!mreg[rr].x) s0 = -1e30f;
                if (!mreg[rr].y) s1 = -1e30f;
                if (!mreg[rr].z) s2 = -1e30f;
                if (!mreg[rr].w) s3 = -1e30f;
            }
            float mx = fmaxf(fmaxf(s0, s1), fmaxf(s2, s3));
            #pragma unroll
            for (int off = 8; off; off >>= 1)
                mx = fmaxf(mx, __shfl_xor_sync(0xffffffffu, mx, off, 16));
            float mnew = fmaxf(mi[rr], mx);
            float corr = __expf(mi[rr] - mnew);
            float4 p;
            p.x = __expf(s0 - mnew);
            p.y = __expf(s1 - mnew);
            p.z = __expf(s2 - mnew);
            p.w = __expf(s3 - mnew);
            float ssum = p.x + p.y + p.z + p.w;
            #pragma unroll
            for (int off = 8; off; off >>= 1)
                ssum += __shfl_xor_sync(0xffffffffu, ssum, off, 16);
            li[rr] = li[rr] * corr + ssum;
            mi[rr] = mnew;
            u64 cd = dup2(corr);
            oA[rr][0] = fmul2(oA[rr][0], cd);
            oA[rr][1] = fmul2(oA[rr][1], cd);
            *reinterpret_cast<float4*>(&Ps[qrow[rr] + kx]) = p;
        }
        __syncthreads();   // Ps visible

        // ---- O += P . V, packed d pairs ----
        {
            const float* vb = Ks + kx;
            #pragma unroll 4
            for (int it = 0; it < 16; it++) {
                ulonglong2 v0 = *reinterpret_cast<const ulonglong2*>(vb);
                ulonglong2 v1 = *reinterpret_cast<const ulonglong2*>(vb + 68);
                ulonglong2 v2 = *reinterpret_cast<const ulonglong2*>(vb + 136);
                ulonglong2 v3 = *reinterpret_cast<const ulonglong2*>(vb + 204);
                vb += 272;
                int c = it * 4;
                #pragma unroll
                for (int rr = 0; rr < 4; rr++) {
                    float4 p4 = *reinterpret_cast<const float4*>(&Ps[qrow[rr] + c]);
                    u64 d;
                    d = dup2(p4.x); oA[rr][0] = ffma2(d, v0.x, oA[rr][0]); oA[rr][1] = ffma2(d, v0.y, oA[rr][1]);
                    d = dup2(p4.y); oA[rr][0] = ffma2(d, v1.x, oA[rr][0]); oA[rr][1] = ffma2(d, v1.y, oA[rr][1]);
                    d = dup2(p4.z); oA[rr][0] = ffma2(d, v2.x, oA[rr][0]); oA[rr][1] = ffma2(d, v2.y, oA[rr][1]);
                    d = dup2(p4.w); oA[rr][0] = ffma2(d, v3.x, oA[rr][0]); oA[rr][1] = ffma2(d, v3.y, oA[rr][1]);
                }
            }
        }
    }

    // normalize + write a in (B, NX, H*HD) layout
    #pragma unroll
    for (int rr = 0; rr < 4; rr++) {
        float inv = 1.f / li[rr];
        float2 o01 = unpk(oA[rr][0]);
        float2 o23 = unpk(oA[rr][1]);
        float4 o = make_float4(o01.x * inv, o01.y * inv, o23.x * inv, o23.y * inv);
        int row = q0 + ty * 4 + rr;
        *reinterpret_cast<float4*>(
            a_out + ((size_t)(b * kNX + row)) * kD + h * kHD + kx) = o;
    }
}

// ---------------------------------------------------------------------------
extern "C" void kernel_launch(void* const* d_in, const int* in_sizes, int n_in,
                              void* d_out, int out_size)
{
    (void)in_sizes; (void)n_in; (void)out_size;
    const float* x    = (const float*)d_in[0];
    const float* c    = (const float*)d_in[1];
    const int*   mask = (const int*)  d_in[2];
    const float* lnw  = (const float*)d_in[3];
    const float* lnb  = (const float*)d_in[4];
    const float* Wq   = (const float*)d_in[5];
    const float* Wo   = (const float*)d_in[6];

    float* o_out  = (float*)d_out;
    float* kv_out = o_out + (size_t)kB * kNX * kD;

    void *p_xn, *p_q, *p_a;
    cudaGetSymbolAddress(&p_xn, g_xn);
    cudaGetSymbolAddress(&p_q,  g_q);
    cudaGetSymbolAddress(&p_a,  g_a);
    float* xn = (float*)p_xn;
    float* q  = (float*)p_q;
    float* a  = (float*)p_a;

    cudaFuncSetAttribute(attn_kernel,
                         cudaFuncAttributeMaxDynamicSharedMemorySize,
                         SMEM_ATTN_BYTES);

    const int M = kB * kNX;   // 1024

    // 1) LayerNorm
    ln_kernel<<<M, 256>>>(x, lnw, lnb, xn);
    // 2) q = xn @ Wq
    sgemm_kernel<<<dim3(kD / 64, M / 128), 256>>>(xn, Wq, q, M, kD, kD);
    // 3) kv0 output (independent)
    kv0_kernel<<<(kB * kH * kNC * kHD / 4) / 256, 256>>>(c, (float4*)kv_out);
    // 4) attention
    attn_kernel<<<kB * kH * (kNX / 64), 256, SMEM_ATTN_BYTES>>>(q, c, mask, a);
    // 5) o = a @ Wo
    sgemm_kernel<<<dim3(kD / 64, M / 128), 256>>>(a, Wo, o_out, M, kD, kD);
}

// round 13
// speedup vs baseline: 1.9869x; 1.9840x over previous
#include <cuda_runtime.h>
#include <math.h>
#include <stdint.h>

static constexpr int kB  = 2;
static constexpr int kNX = 512;
static constexpr int kNC = 4096;
static constexpr int kD  = 1024;
static constexpr int kH  = 16;
static constexpr int kHD = 64;
#define ATT_SCALE 0.125f   // HD^-0.5

// Scratch (allocation-free rule: __device__ globals)
__device__ float g_xn[kB * kNX * kD];
__device__ float g_q [kB * kNX * kD];
__device__ float g_a [kB * kNX * kD];
__device__ uint32_t g_mbits[(size_t)kB * kNX * kNC / 32];

// ---------------------------------------------------------------------------
// packed fp32 helpers (for the fp32 GEMMs)
// ---------------------------------------------------------------------------
using u64 = unsigned long long;

__device__ __forceinline__ u64 ffma2(u64 a, u64 b, u64 c) {
    u64 d;
    asm("fma.rn.f32x2 %0, %1, %2, %3;" : "=l"(d) : "l"(a), "l"(b), "l"(c));
    return d;
}
__device__ __forceinline__ u64 dup2(float v) {
    u64 d;
    asm("mov.b64 %0, {%1, %1};" : "=l"(d) : "f"(v));
    return d;
}
__device__ __forceinline__ float2 unpk(u64 v) {
    float2 f;
    asm("mov.b64 {%0, %1}, %2;" : "=f"(f.x), "=f"(f.y) : "l"(v));
    return f;
}

// ---------------------------------------------------------------------------
// tf32 mma helpers
// ---------------------------------------------------------------------------
__device__ __forceinline__ uint32_t cvt_tf32(float x) {
    uint32_t u;
    asm("cvt.rna.tf32.f32 %0, %1;" : "=r"(u) : "f"(x));
    return u;
}
__device__ __forceinline__ void mma_tf32(float c[4], const uint32_t a[4],
                                         uint32_t b0, uint32_t b1) {
    asm volatile(
        "mma.sync.aligned.m16n8k8.row.col.f32.tf32.tf32.f32 "
        "{%0,%1,%2,%3}, {%4,%5,%6,%7}, {%8,%9}, {%0,%1,%2,%3};"
        : "+f"(c[0]), "+f"(c[1]), "+f"(c[2]), "+f"(c[3])
        : "r"(a[0]), "r"(a[1]), "r"(a[2]), "r"(a[3]), "r"(b0), "r"(b1));
}

// ---------------------------------------------------------------------------
// LayerNorm
// ---------------------------------------------------------------------------
__global__ __launch_bounds__(256) void ln_kernel(
    const float* __restrict__ x, const float* __restrict__ w,
    const float* __restrict__ bb, float* __restrict__ out)
{
    int row = blockIdx.x;
    int tid = threadIdx.x;
    float4 v = reinterpret_cast<const float4*>(x + (size_t)row * kD)[tid];
    float s  = v.x + v.y + v.z + v.w;
    float sq = v.x*v.x + v.y*v.y + v.z*v.z + v.w*v.w;
    #pragma unroll
    for (int o = 16; o; o >>= 1) {
        s  += __shfl_xor_sync(0xffffffffu, s,  o);
        sq += __shfl_xor_sync(0xffffffffu, sq, o);
    }
    __shared__ float ss[8], ssq[8];
    int wid = tid >> 5, lid = tid & 31;
    if (lid == 0) { ss[wid] = s; ssq[wid] = sq; }
    __syncthreads();
    if (wid == 0) {
        s  = (lid < 8) ? ss[lid]  : 0.f;
        sq = (lid < 8) ? ssq[lid] : 0.f;
        #pragma unroll
        for (int o = 4; o; o >>= 1) {
            s  += __shfl_xor_sync(0xffffffffu, s,  o);
            sq += __shfl_xor_sync(0xffffffffu, sq, o);
        }
        if (lid == 0) { ss[0] = s; ssq[0] = sq; }
    }
    __syncthreads();
    float mu   = ss[0] * (1.f / kD);
    float var  = ssq[0] * (1.f / kD) - mu * mu;
    float rstd = rsqrtf(var + 1e-5f);
    float4 w4 = reinterpret_cast<const float4*>(w)[tid];
    float4 b4 = reinterpret_cast<const float4*>(bb)[tid];
    float4 o4;
    o4.x = (v.x - mu) * rstd * w4.x + b4.x;
    o4.y = (v.y - mu) * rstd * w4.y + b4.y;
    o4.z = (v.z - mu) * rstd * w4.z + b4.z;
    o4.w = (v.w - mu) * rstd * w4.w + b4.w;
    reinterpret_cast<float4*>(out + (size_t)row * kD)[tid] = o4;
}

// ---------------------------------------------------------------------------
// SGEMM (f32x2): C[M,N] = A[M,K] @ B[K,N] (unchanged, fp32-exact)
// ---------------------------------------------------------------------------
__device__ __forceinline__ int atrow(int k) { return k * 130 + 2 * (k & 1); }

__global__ __launch_bounds__(256) void sgemm_kernel(
    const float* __restrict__ A, const float* __restrict__ Bm,
    float* __restrict__ C, int M, int N, int K)
{
    __shared__ __align__(16) float At[16 * 130 + 8];
    __shared__ __align__(16) float Bs[16][68];

    int tid = threadIdx.x;
    int tx = tid & 15, ty = tid >> 4;
    int m0 = blockIdx.y * 128, n0 = blockIdx.x * 64;

    u64 acc[8][2];
    #pragma unroll
    for (int i = 0; i < 8; i++) { acc[i][0] = 0ull; acc[i][1] = 0ull; }

    for (int k0 = 0; k0 < K; k0 += 16) {
        #pragma unroll
        for (int j = 0; j < 2; j++) {
            int idx = tid + 256 * j;
            int m = idx >> 2, k4 = idx & 3;
            float4 v = *reinterpret_cast<const float4*>(
                A + (size_t)(m0 + m) * K + k0 + k4 * 4);
            int kk = k4 * 4;
            At[atrow(kk + 0) + m] = v.x;
            At[atrow(kk + 1) + m] = v.y;
            At[atrow(kk + 2) + m] = v.z;
            At[atrow(kk + 3) + m] = v.w;
        }
        {
            int kk = tid >> 4, n4 = tid & 15;
            float4 v = *reinterpret_cast<const float4*>(
                Bm + (size_t)(k0 + kk) * N + n0 + n4 * 4);
            *reinterpret_cast<float4*>(&Bs[kk][n4 * 4]) = v;
        }
        __syncthreads();
        const float* ab = At + ty * 8;
        #pragma unroll
        for (int kk = 0; kk < 16; kk++) {
            ulonglong2 b2 = *reinterpret_cast<const ulonglong2*>(&Bs[kk][tx * 4]);
            float4 a0 = *reinterpret_cast<const float4*>(ab);
            float4 a1 = *reinterpret_cast<const float4*>(ab + 4);
            ab += (kk & 1) ? 128 : 132;
            u64 d;
            d = dup2(a0.x); acc[0][0] = ffma2(d, b2.x, acc[0][0]); acc[0][1] = ffma2(d, b2.y, acc[0][1]);
            d = dup2(a0.y); acc[1][0] = ffma2(d, b2.x, acc[1][0]); acc[1][1] = ffma2(d, b2.y, acc[1][1]);
            d = dup2(a0.z); acc[2][0] = ffma2(d, b2.x, acc[2][0]); acc[2][1] = ffma2(d, b2.y, acc[2][1]);
            d = dup2(a0.w); acc[3][0] = ffma2(d, b2.x, acc[3][0]); acc[3][1] = ffma2(d, b2.y, acc[3][1]);
            d = dup2(a1.x); acc[4][0] = ffma2(d, b2.x, acc[4][0]); acc[4][1] = ffma2(d, b2.y, acc[4][1]);
            d = dup2(a1.y); acc[5][0] = ffma2(d, b2.x, acc[5][0]); acc[5][1] = ffma2(d, b2.y, acc[5][1]);
            d = dup2(a1.z); acc[6][0] = ffma2(d, b2.x, acc[6][0]); acc[6][1] = ffma2(d, b2.y, acc[6][1]);
            d = dup2(a1.w); acc[7][0] = ffma2(d, b2.x, acc[7][0]); acc[7][1] = ffma2(d, b2.y, acc[7][1]);
        }
        __syncthreads();
    }
    #pragma unroll
    for (int rr = 0; rr < 8; rr++) {
        float2 c01 = unpk(acc[rr][0]);
        float2 c23 = unpk(acc[rr][1]);
        float4 o = make_float4(c01.x, c01.y, c23.x, c23.y);
        *reinterpret_cast<float4*>(
            C + (size_t)(m0 + ty * 8 + rr) * N + n0 + tx * 4) = o;
    }
}

// ---------------------------------------------------------------------------
// kv0: out[b][h][n][d] = c[b][n][h*64+d]
// ---------------------------------------------------------------------------
__global__ __launch_bounds__(256) void kv0_kernel(
    const float* __restrict__ c, float4* __restrict__ out)
{
    int i = blockIdx.x * 256 + threadIdx.x;
    int d4 = i & 15;
    int n  = (i >> 4) & (kNC - 1);
    int h  = (i >> 16) & (kH - 1);
    int b  = i >> 20;
    const float4* src = reinterpret_cast<const float4*>(c);
    out[i] = src[(size_t)(b * kNC + n) * (kD / 4) + h * 16 + d4];
}

// ---------------------------------------------------------------------------
// mask bit-pack prepass: 32 int32 -> 1 uint32 via ballot
// ---------------------------------------------------------------------------
__global__ __launch_bounds__(256) void maskbits_kernel(
    const int* __restrict__ m, uint32_t* __restrict__ bits)
{
    int i = blockIdx.x * 256 + threadIdx.x;
    uint32_t b = __ballot_sync(0xffffffffu, m[i] != 0);
    if ((threadIdx.x & 31) == 0) bits[i >> 5] = b;
}

// ---------------------------------------------------------------------------
// Flash attention, tf32 mma.sync (m16n8k8). Block = 128 thr (4 warps),
// each warp = 16 q rows x 64 keys per tile. Grid = B*H*(NX/64) = 256.
// smem: Qs/Ps [64][68] | Ks [64][68] | Vs [64][72]  (tf32-rounded fp32 bits)
// ---------------------------------------------------------------------------
static constexpr int S_QS  = 0;              // 64*68, reused as Ps
static constexpr int S_KS  = 64 * 68;        // 4352
static constexpr int S_VS  = S_KS + 64 * 68; // 8704
static constexpr int S_TOT = S_VS + 64 * 72; // 13312 floats
static constexpr int SMEM_ATTN_BYTES = S_TOT * 4;

__global__ __launch_bounds__(128) void attn_kernel(
    const float* __restrict__ q_s, const float* __restrict__ ctx,
    const uint32_t* __restrict__ bm, float* __restrict__ a_out)
{
    extern __shared__ float sm[];
    float* Qs = sm + S_QS;   // staging for Q, then Ps
    float* Ks = sm + S_KS;
    float* Vs = sm + S_VS;
    float* Ps = Qs;

    int tid  = threadIdx.x;
    int lane = tid & 31, w = tid >> 5;
    int gr = lane >> 2, q = lane & 3;
    int qt = blockIdx.x & 7;
    int h  = (blockIdx.x >> 3) & 15;
    int b  = blockIdx.x >> 7;
    int q0 = qt * 64;

    // ---- stage Q tile (scaled + tf32-rounded) ----
    {
        const float* src = q_s + ((size_t)(b * kNX + q0)) * kD + h * kHD;
        #pragma unroll
        for (int j = 0; j < 8; j++) {
            int idx = tid + 128 * j;
            int r = idx >> 4, c4 = idx & 15;
            float4 v = *reinterpret_cast<const float4*>(src + (size_t)r * kD + c4 * 4);
            uint4 u;
            u.x = cvt_tf32(v.x * ATT_SCALE);
            u.y = cvt_tf32(v.y * ATT_SCALE);
            u.z = cvt_tf32(v.z * ATT_SCALE);
            u.w = cvt_tf32(v.w * ATT_SCALE);
            *reinterpret_cast<uint4*>(&Qs[r * 68 + c4 * 4]) = u;
        }
    }
    __syncthreads();

    // ---- extract Q A-fragments (held in regs for whole kernel) ----
    uint32_t qa[8][4];
    int qr0 = (w * 16 + gr) * 68;
    int qr1 = qr0 + 8 * 68;
    #pragma unroll
    for (int s = 0; s < 8; s++) {
        qa[s][0] = __float_as_uint(Qs[qr0 + s * 8 + q]);
        qa[s][1] = __float_as_uint(Qs[qr1 + s * 8 + q]);
        qa[s][2] = __float_as_uint(Qs[qr0 + s * 8 + q + 4]);
        qa[s][3] = __float_as_uint(Qs[qr1 + s * 8 + q + 4]);
    }
    __syncthreads();   // Qs now free -> Ps

    float o[8][4];
    #pragma unroll
    for (int dt = 0; dt < 8; dt++)
        #pragma unroll
        for (int c = 0; c < 4; c++) o[dt][c] = 0.f;
    float mi0 = -1e30f, mi1 = -1e30f, li0 = 0.f, li1 = 0.f;

    const uint32_t* mrow0 = bm + ((size_t)(b * kNX + q0 + w * 16 + gr)) * (kNC / 32);
    const uint32_t* mrow1 = mrow0 + 8 * (kNC / 32);

    const int NT = kNX / 64 + kNC / 64;   // 72
    for (int t = 0; t < NT; t++) {
        __syncthreads();   // prev-tile PV reads done before refill
        const float* src = (t < 8)
            ? q_s + ((size_t)(b * kNX + t * 64)) * kD + h * kHD
            : ctx + ((size_t)(b * kNC + (t - 8) * 64)) * kD + h * kHD;
        #pragma unroll
        for (int j = 0; j < 8; j++) {
            int idx = tid + 128 * j;
            int r = idx >> 4, c4 = idx & 15;
            float4 v = *reinterpret_cast<const float4*>(src + (size_t)r * kD + c4 * 4);
            uint4 u;
            u.x = cvt_tf32(v.x); u.y = cvt_tf32(v.y);
            u.z = cvt_tf32(v.z); u.w = cvt_tf32(v.w);
            *reinterpret_cast<uint4*>(&Ks[r * 68 + c4 * 4]) = u;
            *reinterpret_cast<uint4*>(&Vs[r * 72 + c4 * 4]) = u;
        }
        bool masked = (t >= 8);
        uint2 mw0, mw1;
        if (masked) {
            mw0 = *reinterpret_cast<const uint2*>(mrow0 + (t - 8) * 2);
            mw1 = *reinterpret_cast<const uint2*>(mrow1 + (t - 8) * 2);
        }
        __syncthreads();

        // ---- S = Q . K^T : 8 n-tiles x 8 k-steps of m16n8k8 ----
        float s[8][4];
        const float* kb = Ks + gr * 68 + q;
        #pragma unroll
        for (int j = 0; j < 8; j++) {
            s[j][0] = 0.f; s[j][1] = 0.f; s[j][2] = 0.f; s[j][3] = 0.f;
            const float* kj = kb + j * (8 * 68);
            #pragma unroll
            for (int ks = 0; ks < 8; ks++) {
                uint32_t b0 = __float_as_uint(kj[ks * 8]);
                uint32_t b1 = __float_as_uint(kj[ks * 8 + 4]);
                mma_tf32(s[j], qa[ks], b0, b1);
            }
        }

        // ---- mask ----
        if (masked) {
            #pragma unroll
            for (int j = 0; j < 8; j++) {
                uint32_t w0 = (j < 4) ? mw0.x : mw0.y;
                uint32_t w1 = (j < 4) ? mw1.x : mw1.y;
                int bit = (8 * j + 2 * q) & 31;
                if (!((w0 >> bit) & 1u))       s[j][0] = -1e30f;
                if (!((w0 >> (bit + 1)) & 1u)) s[j][1] = -1e30f;
                if (!((w1 >> bit) & 1u))       s[j][2] = -1e30f;
                if (!((w1 >> (bit + 1)) & 1u)) s[j][3] = -1e30f;
            }
        }

        // ---- online softmax (rows g and g+8; 4 lanes per row) ----
        float mx0 = -1e30f, mx1 = -1e30f;
        #pragma unroll
        for (int j = 0; j < 8; j++) {
            mx0 = fmaxf(mx0, fmaxf(s[j][0], s[j][1]));
            mx1 = fmaxf(mx1, fmaxf(s[j][2], s[j][3]));
        }
        mx0 = fmaxf(mx0, __shfl_xor_sync(0xffffffffu, mx0, 1));
        mx0 = fmaxf(mx0, __shfl_xor_sync(0xffffffffu, mx0, 2));
        mx1 = fmaxf(mx1, __shfl_xor_sync(0xffffffffu, mx1, 1));
        mx1 = fmaxf(mx1, __shfl_xor_sync(0xffffffffu, mx1, 2));
        float mn0 = fmaxf(mi0, mx0), mn1 = fmaxf(mi1, mx1);
        float corr0 = __expf(mi0 - mn0), corr1 = __expf(mi1 - mn1);
        mi0 = mn0; mi1 = mn1;

        float sum0 = 0.f, sum1 = 0.f;
        int pr0 = qr0, pr1 = qr1;
        #pragma unroll
        for (int j = 0; j < 8; j++) {
            float p0 = __expf(s[j][0] - mn0);
            float p1 = __expf(s[j][1] - mn0);
            float p2 = __expf(s[j][2] - mn1);
            float p3 = __expf(s[j][3] - mn1);
            sum0 += p0 + p1;
            sum1 += p2 + p3;
            float2 st0, st1;
            st0.x = __uint_as_float(cvt_tf32(p0));
            st0.y = __uint_as_float(cvt_tf32(p1));
            st1.x = __uint_as_float(cvt_tf32(p2));
            st1.y = __uint_as_float(cvt_tf32(p3));
            *reinterpret_cast<float2*>(&Ps[pr0 + 8 * j + 2 * q]) = st0;
            *reinterpret_cast<float2*>(&Ps[pr1 + 8 * j + 2 * q]) = st1;
        }
        sum0 += __shfl_xor_sync(0xffffffffu, sum0, 1);
        sum0 += __shfl_xor_sync(0xffffffffu, sum0, 2);
        sum1 += __shfl_xor_sync(0xffffffffu, sum1, 1);
        sum1 += __shfl_xor_sync(0xffffffffu, sum1, 2);
        li0 = li0 * corr0 + sum0;
        li1 = li1 * corr1 + sum1;
        #pragma unroll
        for (int dt = 0; dt < 8; dt++) {
            o[dt][0] *= corr0; o[dt][1] *= corr0;
            o[dt][2] *= corr1; o[dt][3] *= corr1;
        }
        __syncwarp();   // Ps is per-warp private

        // ---- O += P . V : 8 k-steps x 8 d-tiles ----
        const float* vb = Vs + q * 72 + gr;
        #pragma unroll
        for (int ks = 0; ks < 8; ks++) {
            uint32_t pa[4];
            pa[0] = __float_as_uint(Ps[pr0 + ks * 8 + q]);
            pa[1] = __float_as_uint(Ps[pr1 + ks * 8 + q]);
            pa[2] = __float_as_uint(Ps[pr0 + ks * 8 + q + 4]);
            pa[3] = __float_as_uint(Ps[pr1 + ks * 8 + q + 4]);
            const float* vk = vb + ks * (8 * 72);
            #pragma unroll
            for (int dt = 0; dt < 8; dt++) {
                uint32_t b0 = __float_as_uint(vk[dt * 8]);
                uint32_t b1 = __float_as_uint(vk[4 * 72 + dt * 8]);
                mma_tf32(o[dt], pa, b0, b1);
            }
        }
    }

    // ---- normalize + write a in (B, NX, H*HD) layout ----
    float inv0 = 1.f / li0, inv1 = 1.f / li1;
    int row0 = q0 + w * 16 + gr;
    float* d0 = a_out + ((size_t)(b * kNX + row0)) * kD + h * kHD + 2 * q;
    float* d1 = d0 + 8 * kD;
    #pragma unroll
    for (int dt = 0; dt < 8; dt++) {
        float2 v0 = make_float2(o[dt][0] * inv0, o[dt][1] * inv0);
        float2 v1 = make_float2(o[dt][2] * inv1, o[dt][3] * inv1);
        *reinterpret_cast<float2*>(d0 + dt * 8) = v0;
        *reinterpret_cast<float2*>(d1 + dt * 8) = v1;
    }
}

// ---------------------------------------------------------------------------
extern "C" void kernel_launch(void* const* d_in, const int* in_sizes, int n_in,
                              void* d_out, int out_size)
{
    (void)in_sizes; (void)n_in; (void)out_size;
    const float* x    = (const float*)d_in[0];
    const float* c    = (const float*)d_in[1];
    const int*   mask = (const int*)  d_in[2];
    const float* lnw  = (const float*)d_in[3];
    const float* lnb  = (const float*)d_in[4];
    const float* Wq   = (const float*)d_in[5];
    const float* Wo   = (const float*)d_in[6];

    float* o_out  = (float*)d_out;
    float* kv_out = o_out + (size_t)kB * kNX * kD;

    void *p_xn, *p_q, *p_a, *p_mb;
    cudaGetSymbolAddress(&p_xn, g_xn);
    cudaGetSymbolAddress(&p_q,  g_q);
    cudaGetSymbolAddress(&p_a,  g_a);
    cudaGetSymbolAddress(&p_mb, g_mbits);
    float* xn = (float*)p_xn;
    float* q  = (float*)p_q;
    float* a  = (float*)p_a;
    uint32_t* mb = (uint32_t*)p_mb;

    cudaFuncSetAttribute(attn_kernel,
                         cudaFuncAttributeMaxDynamicSharedMemorySize,
                         SMEM_ATTN_BYTES);

    const int M = kB * kNX;   // 1024

    // 1) mask bit-pack (independent)
    maskbits_kernel<<<(kB * kNX * kNC) / 256, 256>>>(mask, mb);
    // 2) LayerNorm
    ln_kernel<<<M, 256>>>(x, lnw, lnb, xn);
    // 3) q = xn @ Wq
    sgemm_kernel<<<dim3(kD / 64, M / 128), 256>>>(xn, Wq, q, M, kD, kD);
    // 4) kv0 output (independent)
    kv0_kernel<<<(kB * kH * kNC * kHD / 4) / 256, 256>>>(c, (float4*)kv_out);
    // 5) attention (tf32 tensor cores)
    attn_kernel<<<kB * kH * (kNX / 64), 128, SMEM_ATTN_BYTES>>>(q, c, mb, a);
    // 6) o = a @ Wo
    sgemm_kernel<<<dim3(kD / 64, M / 128), 256>>>(a, Wo, o_out, M, kD, kD);
}